// round 11
// baseline (speedup 1.0000x reference)
#include <cuda_runtime.h>
#include <cuda_bf16.h>
#include <math.h>
#include <stdint.h>

#define NN 50000
#define NE 1600000
#define C 128
#define ETILE 128
#define NTILES (NE / ETILE)
#define ETILE2 64
#define NTILES2 (NE / ETILE2)
#define NROWT ((NN + 127) / 128)
#define AST 136
#define ASTB (AST * 2)

// ---------------- scratch ----------------
__device__ float g_h[NN * C];
__device__ float g_hn[NN * C];
__device__ float g_hs[NN * C];
__device__ float g_hd[NN * C];
__device__ float g_hagg[NN * C];
__device__ float g_xagg[NN * 3];
__device__ float g_coord[NN * 3];

__device__ __forceinline__ float silu_f(float x) { return x * (1.f / (1.f + __expf(-x))); }
__device__ __forceinline__ float gelu_f(float x) { return 0.5f * x * (1.f + erff(x * 0.70710678118654752f)); }

__device__ __forceinline__ void red2(float* a, float x, float y) {
    asm volatile("red.global.add.v2.f32 [%0], {%1,%2};" :: "l"(a), "f"(x), "f"(y) : "memory");
}
__device__ __forceinline__ uint32_t smem_u32(const void* p) {
    uint32_t a;
    asm("{ .reg .u64 t; cvta.to.shared.u64 t, %1; cvt.u32.u64 %0, t; }" : "=r"(a) : "l"(p));
    return a;
}
__device__ __forceinline__ void ldm_x4(uint32_t& r0, uint32_t& r1, uint32_t& r2, uint32_t& r3, uint32_t addr) {
    asm volatile("ldmatrix.sync.aligned.m8n8.x4.shared.b16 {%0,%1,%2,%3}, [%4];"
                 : "=r"(r0), "=r"(r1), "=r"(r2), "=r"(r3) : "r"(addr));
}
__device__ __forceinline__ void mma_bf16(float* c, uint32_t a0, uint32_t a1, uint32_t a2, uint32_t a3,
                                         uint32_t b0, uint32_t b1) {
    asm volatile("mma.sync.aligned.m16n8k16.row.col.f32.bf16.bf16.f32 "
                 "{%0,%1,%2,%3},{%4,%5,%6,%7},{%8,%9},{%0,%1,%2,%3};"
                 : "+f"(c[0]), "+f"(c[1]), "+f"(c[2]), "+f"(c[3])
                 : "r"(a0), "r"(a1), "r"(a2), "r"(a3), "r"(b0), "r"(b1));
}

__device__ __forceinline__ void st_split(char* smem, uint32_t offH, uint32_t offL,
                                         int r, int c, float v0, float v1) {
    uint32_t o = (uint32_t)(r * ASTB + c * 2);
    __nv_bfloat162 hi, lo;
    hi.x = __float2bfloat16(v0);
    hi.y = __float2bfloat16(v1);
    lo.x = __float2bfloat16(v0 - __bfloat162float(hi.x));
    lo.y = __float2bfloat16(v1 - __bfloat162float(hi.y));
    *(__nv_bfloat162*)(smem + offH + o) = hi;
    *(__nv_bfloat162*)(smem + offL + o) = lo;
}
__device__ __forceinline__ void st_split2(char* smem, uint32_t offH, uint32_t offL,
                                          int r, int c, float v0, float v1, float v2, float v3) {
    uint32_t o = (uint32_t)(r * ASTB + c * 2);
    __nv_bfloat162 h0, h1, l0, l1;
    h0.x = __float2bfloat16(v0); h0.y = __float2bfloat16(v1);
    h1.x = __float2bfloat16(v2); h1.y = __float2bfloat16(v3);
    l0.x = __float2bfloat16(v0 - __bfloat162float(h0.x));
    l0.y = __float2bfloat16(v1 - __bfloat162float(h0.y));
    l1.x = __float2bfloat16(v2 - __bfloat162float(h1.x));
    l1.y = __float2bfloat16(v3 - __bfloat162float(h1.y));
    uint2 H, L;
    H.x = *(uint32_t*)&h0; H.y = *(uint32_t*)&h1;
    L.x = *(uint32_t*)&l0; L.y = *(uint32_t*)&l1;
    *(uint2*)(smem + offH + o) = H;
    *(uint2*)(smem + offL + o) = L;
}
__device__ __forceinline__ void st_wsplit(char* smem, uint32_t offH, uint32_t offL, uint32_t o, float w) {
    __nv_bfloat16 h1 = __float2bfloat16(w);
    *(__nv_bfloat16*)(smem + offH + o) = h1;
    *(__nv_bfloat16*)(smem + offL + o) = __float2bfloat16(w - __bfloat162float(h1));
}

// m16n64 bf16 MMA pass over K=128 (A rows wm*16..wm*16+15, B cols wn*64..)
__device__ __forceinline__ void mma_pass(float acc[8][4], uint32_t sb, uint32_t aoff, uint32_t boff,
                                         int wm, int wn, int lane) {
    uint32_t a_base = sb + aoff + (uint32_t)((wm * 16 + (lane & 15)) * ASTB + ((lane >> 4) << 3) * 2);
    uint32_t b_base = sb + boff + (uint32_t)((wn * 64 + ((lane >> 4) << 3) + (lane & 7)) * ASTB
                                             + (((lane >> 3) & 1) << 3) * 2);
#pragma unroll
    for (int k8 = 0; k8 < 8; k8++) {
        uint32_t a0, a1, a2, a3;
        ldm_x4(a0, a1, a2, a3, a_base + k8 * 32);
#pragma unroll
        for (int j4 = 0; j4 < 4; j4++) {
            uint32_t b0, b1, b2, b3;
            ldm_x4(b0, b1, b2, b3, b_base + (uint32_t)(j4 * 16 * ASTB) + k8 * 32);
            mma_bf16(acc[2 * j4], a0, a1, a2, a3, b0, b1);
            mma_bf16(acc[2 * j4 + 1], a0, a1, a2, a3, b2, b3);
        }
    }
}
__device__ __forceinline__ void zero_acc(float acc[8][4]) {
#pragma unroll
    for (int j = 0; j < 8; j++) { acc[j][0] = acc[j][1] = acc[j][2] = acc[j][3] = 0.f; }
}

#define TILE_B   (128 * ASTB)          // 34816
#define TILE_A64 (64 * ASTB)           // 17408

// ---- CO edge kernel smem layout (R5/R7, proven) ----
#define OFF_VEC  0
#define OFF_GEO  2560
#define OFF_CM   4608
#define OFF_AHI  5120
#define OFF_ALO  (OFF_AHI + TILE_B)
#define OFF_B1H  (OFF_ALO + TILE_B)
#define OFF_B1L  (OFF_B1H + TILE_B)
#define OFF_B2H  (OFF_B1L + TILE_B)
#define OFF_B2L  (OFF_B2H + TILE_B)
#define SMEM_EDGE_CO (OFF_B2L + TILE_B)

// ---- NC edge kernel smem layout (256 threads, 2 CTAs/SM) ----
#define NC_VEC 0
#define NC_AHI 2048
#define NC_ALO (NC_AHI + TILE_A64)
#define NC_B1H (NC_ALO + TILE_A64)
#define NC_B1L (NC_B1H + TILE_B)
#define SMEM_NC (NC_B1L + TILE_B)      // 106496

// ---------------- NC edge kernel: 256 threads, ETILE2=64, 2 CTAs/SM ----------------
__global__ __launch_bounds__(256, 2) void edge_nc_kernel(
    const int* __restrict__ src, const int* __restrict__ dst,
    const float* __restrict__ X,
    const float* __restrict__ hs, const float* __restrict__ hd,
    const float* __restrict__ wr, const float* __restrict__ eb1,
    const float* __restrict__ ew2, const float* __restrict__ eb2,
    float* __restrict__ hagg)
{
    extern __shared__ char smem[];
    uint32_t sb = smem_u32(smem);
    float* s_vec = (float*)(smem + NC_VEC);
    int tid = threadIdx.x, warp = tid >> 5, lane = tid & 31;
    int wm = warp >> 1, wn = warp & 1;
    int g = lane >> 2, q4 = lane & 3;

    if (tid < C) {
        s_vec[tid] = wr[tid];
        s_vec[C + tid] = eb1[tid];
        s_vec[2 * C + tid] = eb2[tid];
    }
    for (int idx = tid; idx < C * C; idx += 256) {
        int n = idx >> 7, k = idx & 127;
        uint32_t o = (uint32_t)(n * ASTB + k * 2);
        st_wsplit(smem, NC_B1H, NC_B1L, o, ew2[k * C + n]);
    }
    __syncthreads();

    int el = tid >> 2, cg = (tid & 3) << 5;   // edge-local row [0,64), col group

    for (int tile = blockIdx.x; tile < NTILES2; tile += gridDim.x) {
        // ---- m1 = silu(hs[src] + hd[dst] + rad*wr + eb1) -> A (bf16 split) ----
        {
            int e = tile * ETILE2 + el;
            int si = src[e], di = dst[e];
            float ax = X[si * 3 + 0] - X[di * 3 + 0];
            float ay = X[si * 3 + 1] - X[di * 3 + 1];
            float az = X[si * 3 + 2] - X[di * 3 + 2];
            float rad = ax * ax + ay * ay + az * az;
            const float4* ps = (const float4*)(hs + (size_t)si * C + cg);
            const float4* pd = (const float4*)(hd + (size_t)di * C + cg);
#pragma unroll
            for (int qq = 0; qq < 8; qq++) {
                float4 a = ps[qq], b = pd[qq];
                int c = cg + qq * 4;
                float v0 = silu_f(a.x + b.x + rad * s_vec[c + 0] + s_vec[C + c + 0]);
                float v1 = silu_f(a.y + b.y + rad * s_vec[c + 1] + s_vec[C + c + 1]);
                float v2 = silu_f(a.z + b.z + rad * s_vec[c + 2] + s_vec[C + c + 2]);
                float v3 = silu_f(a.w + b.w + rad * s_vec[c + 3] + s_vec[C + c + 3]);
                st_split2(smem, NC_AHI, NC_ALO, el, c, v0, v1, v2, v3);
            }
        }
        __syncthreads();
        // ---- MMA: D = m1 @ ew2 (3-pass split) ----
        float acc[8][4];
        zero_acc(acc);
        mma_pass(acc, sb, NC_AHI, NC_B1H, wm, wn, lane);
        mma_pass(acc, sb, NC_AHI, NC_B1L, wm, wn, lane);
        mma_pass(acc, sb, NC_ALO, NC_B1H, wm, wn, lane);
        __syncthreads();   // A tiles free for next tile's m1
        // ---- epilogue: m2 = silu(D + eb2) -> hagg atomics ----
        {
            int r0 = wm * 16 + g, r1 = r0 + 8;
            int d0 = dst[tile * ETILE2 + r0], d1 = dst[tile * ETILE2 + r1];
            float* h0 = hagg + (size_t)d0 * C;
            float* h1 = hagg + (size_t)d1 * C;
#pragma unroll
            for (int j = 0; j < 8; j++) {
                int col = wn * 64 + j * 8 + q4 * 2;
                float b0 = s_vec[2 * C + col], b1 = s_vec[2 * C + col + 1];
                red2(h0 + col, silu_f(acc[j][0] + b0), silu_f(acc[j][1] + b1));
                red2(h1 + col, silu_f(acc[j][2] + b0), silu_f(acc[j][3] + b1));
            }
        }
    }
}

// ---------------- CO edge kernel (EXACT R5/R7, proven) ----------------
__global__ __launch_bounds__(512, 1) void edge_co_kernel(
    const int* __restrict__ src, const int* __restrict__ dst,
    const float* __restrict__ X,
    const float* __restrict__ hs, const float* __restrict__ hd,
    const float* __restrict__ wr, const float* __restrict__ eb1,
    const float* __restrict__ ew2, const float* __restrict__ eb2,
    const float* __restrict__ cw1, const float* __restrict__ cb1,
    const float* __restrict__ cw2,
    float* __restrict__ hagg, float* __restrict__ xagg)
{
    extern __shared__ char smem[];
    uint32_t sb = smem_u32(smem);
    float* s_vec = (float*)(smem + OFF_VEC);
    float4* s_geo = (float4*)(smem + OFF_GEO);
    float* s_cm = (float*)(smem + OFF_CM);
    int tid = threadIdx.x, warp = tid >> 5, lane = tid & 31;
    int wm = warp >> 1, wn = warp & 1;
    int g = lane >> 2, q4 = lane & 3;

    if (tid < C) {
        s_vec[tid] = wr[tid];
        s_vec[C + tid] = eb1[tid];
        s_vec[2 * C + tid] = eb2[tid];
        s_vec[3 * C + tid] = cb1[tid];
        s_vec[4 * C + tid] = cw2[tid];
    }
    if (tid < ETILE) s_cm[tid] = 0.f;
    for (int idx = tid; idx < C * C; idx += 512) {
        int n = idx >> 7, k = idx & 127;
        uint32_t o = (uint32_t)(n * ASTB + k * 2);
        st_wsplit(smem, OFF_B1H, OFF_B1L, o, ew2[k * C + n]);
        st_wsplit(smem, OFF_B2H, OFF_B2L, o, cw1[k * C + n]);
    }
    __syncthreads();

    int el = tid >> 2, cg = (tid & 3) << 5;

    for (int tile = blockIdx.x; tile < NTILES; tile += gridDim.x) {
        {
            int e = tile * ETILE + el;
            int si = src[e], di = dst[e];
            float ax = X[si * 3 + 0] - X[di * 3 + 0];
            float ay = X[si * 3 + 1] - X[di * 3 + 1];
            float az = X[si * 3 + 2] - X[di * 3 + 2];
            float rad = ax * ax + ay * ay + az * az;
            if ((tid & 3) == 0)
                s_geo[el] = make_float4(ax, ay, az, 1.f / (sqrtf(rad) + 1e-30f));
            const float4* ps = (const float4*)(hs + (size_t)si * C + cg);
            const float4* pd = (const float4*)(hd + (size_t)di * C + cg);
#pragma unroll
            for (int qq = 0; qq < 8; qq++) {
                float4 a = ps[qq], b = pd[qq];
                int c = cg + qq * 4;
                float v0 = silu_f(a.x + b.x + rad * s_vec[c + 0] + s_vec[C + c + 0]);
                float v1 = silu_f(a.y + b.y + rad * s_vec[c + 1] + s_vec[C + c + 1]);
                float v2 = silu_f(a.z + b.z + rad * s_vec[c + 2] + s_vec[C + c + 2]);
                float v3 = silu_f(a.w + b.w + rad * s_vec[c + 3] + s_vec[C + c + 3]);
                st_split(smem, OFF_AHI, OFF_ALO, el, c, v0, v1);
                st_split(smem, OFF_AHI, OFF_ALO, el, c + 2, v2, v3);
            }
        }
        __syncthreads();
        float acc[8][4];
        zero_acc(acc);
        mma_pass(acc, sb, OFF_AHI, OFF_B1H, wm, wn, lane);
        mma_pass(acc, sb, OFF_AHI, OFF_B1L, wm, wn, lane);
        mma_pass(acc, sb, OFF_ALO, OFF_B1H, wm, wn, lane);
        __syncthreads();
        {
            int r0 = wm * 16 + g, r1 = r0 + 8;
            int d0 = dst[tile * ETILE + r0], d1 = dst[tile * ETILE + r1];
            float* h0 = hagg + (size_t)d0 * C;
            float* h1 = hagg + (size_t)d1 * C;
#pragma unroll
            for (int j = 0; j < 8; j++) {
                int col = wn * 64 + j * 8 + q4 * 2;
                float b0 = s_vec[2 * C + col], b1 = s_vec[2 * C + col + 1];
                float m00 = silu_f(acc[j][0] + b0), m01 = silu_f(acc[j][1] + b1);
                float m10 = silu_f(acc[j][2] + b0), m11 = silu_f(acc[j][3] + b1);
                red2(h0 + col, m00, m01);
                red2(h1 + col, m10, m11);
                st_split(smem, OFF_AHI, OFF_ALO, r0, col, m00, m01);
                st_split(smem, OFF_AHI, OFF_ALO, r1, col, m10, m11);
            }
        }
        __syncthreads();
        zero_acc(acc);
        mma_pass(acc, sb, OFF_AHI, OFF_B2H, wm, wn, lane);
        mma_pass(acc, sb, OFF_AHI, OFF_B2L, wm, wn, lane);
        mma_pass(acc, sb, OFF_ALO, OFF_B2H, wm, wn, lane);
        {
            float p0 = 0.f, p1 = 0.f;
#pragma unroll
            for (int j = 0; j < 8; j++) {
                int col = wn * 64 + j * 8 + q4 * 2;
                float cb0 = s_vec[3 * C + col], cb1v = s_vec[3 * C + col + 1];
                float w0 = s_vec[4 * C + col], w1 = s_vec[4 * C + col + 1];
                p0 += silu_f(acc[j][0] + cb0) * w0 + silu_f(acc[j][1] + cb1v) * w1;
                p1 += silu_f(acc[j][2] + cb0) * w0 + silu_f(acc[j][3] + cb1v) * w1;
            }
            int r0 = wm * 16 + g;
            atomicAdd(&s_cm[r0], p0);
            atomicAdd(&s_cm[r0 + 8], p1);
        }
        __syncthreads();
        if (tid < ETILE) {
            float cm = s_cm[tid];
            s_cm[tid] = 0.f;
            float4 gg = s_geo[tid];
            int d2 = dst[tile * ETILE + tid];
            float s = cm * gg.w;
            atomicAdd(&xagg[d2 * 3 + 0], s * gg.x);
            atomicAdd(&xagg[d2 * 3 + 1], s * gg.y);
            atomicAdd(&xagg[d2 * 3 + 2], s * gg.z);
        }
        __syncthreads();
    }
}

// ================= tensorized node-side kernels (R7, passing) =================
#define P_AHI 0
#define P_ALO (P_AHI + TILE_B)
#define P_SH  (P_ALO + TILE_B)
#define P_SL  (P_SH + TILE_B)
#define P_DH  (P_SL + TILE_B)
#define P_DL  (P_DH + TILE_B)
#define SMEM_PRE (P_DL + TILE_B)

__global__ __launch_bounds__(512, 1) void pre_mma_kernel(
    const float* __restrict__ h, const float* __restrict__ ew1,
    float* __restrict__ hs, float* __restrict__ hd)
{
    extern __shared__ char smem[];
    uint32_t sb = smem_u32(smem);
    int tid = threadIdx.x, warp = tid >> 5, lane = tid & 31;
    int wm = warp >> 1, wn = warp & 1, g = lane >> 2, q4 = lane & 3;
    int row0 = blockIdx.x * 128;

    for (int idx = tid; idx < C * C; idx += 512) {
        int n = idx >> 7, k = idx & 127;
        uint32_t o = (uint32_t)(n * ASTB + k * 2);
        st_wsplit(smem, P_SH, P_SL, o, ew1[k * C + n]);
        st_wsplit(smem, P_DH, P_DL, o, ew1[(C + k) * C + n]);
    }
    {
        int el = tid >> 2, cg = (tid & 3) << 5;
        int rg = min(row0 + el, NN - 1);
        const float4* pa = (const float4*)(h + (size_t)rg * C + cg);
#pragma unroll
        for (int qq = 0; qq < 8; qq++) {
            float4 a = pa[qq];
            int c = cg + qq * 4;
            st_split(smem, P_AHI, P_ALO, el, c, a.x, a.y);
            st_split(smem, P_AHI, P_ALO, el, c + 2, a.z, a.w);
        }
    }
    __syncthreads();

    int r0 = wm * 16 + g, r1 = r0 + 8;
    bool v0 = (row0 + r0) < NN, v1 = (row0 + r1) < NN;
    float acc[8][4];

    zero_acc(acc);
    mma_pass(acc, sb, P_AHI, P_SH, wm, wn, lane);
    mma_pass(acc, sb, P_AHI, P_SL, wm, wn, lane);
    mma_pass(acc, sb, P_ALO, P_SH, wm, wn, lane);
#pragma unroll
    for (int j = 0; j < 8; j++) {
        int col = wn * 64 + j * 8 + q4 * 2;
        if (v0) { hs[(size_t)(row0 + r0) * C + col] = acc[j][0]; hs[(size_t)(row0 + r0) * C + col + 1] = acc[j][1]; }
        if (v1) { hs[(size_t)(row0 + r1) * C + col] = acc[j][2]; hs[(size_t)(row0 + r1) * C + col + 1] = acc[j][3]; }
    }
    zero_acc(acc);
    mma_pass(acc, sb, P_AHI, P_DH, wm, wn, lane);
    mma_pass(acc, sb, P_AHI, P_DL, wm, wn, lane);
    mma_pass(acc, sb, P_ALO, P_DH, wm, wn, lane);
#pragma unroll
    for (int j = 0; j < 8; j++) {
        int col = wn * 64 + j * 8 + q4 * 2;
        if (v0) { hd[(size_t)(row0 + r0) * C + col] = acc[j][0]; hd[(size_t)(row0 + r0) * C + col + 1] = acc[j][1]; }
        if (v1) { hd[(size_t)(row0 + r1) * C + col] = acc[j][2]; hd[(size_t)(row0 + r1) * C + col + 1] = acc[j][3]; }
    }
}

#define N_VEC  0
#define N_MU   2048
#define N_S2   2560
#define N_AHI  4096
#define N_ALO  (N_AHI + TILE_B)
#define N_BAH  (N_ALO + TILE_B)
#define N_BAL  (N_BAH + TILE_B)
#define N_BBH  (N_BAL + TILE_B)
#define N_BBL  (N_BBH + TILE_B)
#define SMEM_NODE (N_BBL + TILE_B)

template <bool DEC>
__global__ __launch_bounds__(512, 1) void node_mma_kernel(
    const float* __restrict__ h, const float* __restrict__ hagg,
    const float* __restrict__ nw1, const float* __restrict__ nb1,
    const float* __restrict__ nw2, const float* __restrict__ nb2,
    const float* __restrict__ lg, const float* __restrict__ lb,
    float* __restrict__ out)
{
    extern __shared__ char smem[];
    uint32_t sb = smem_u32(smem);
    float* s_vec = (float*)(smem + N_VEC);
    float* s_mu = (float*)(smem + N_MU);
    float* s_s2 = (float*)(smem + N_S2);
    int tid = threadIdx.x, warp = tid >> 5, lane = tid & 31;
    int wm = warp >> 1, wn = warp & 1, g = lane >> 2, q4 = lane & 3;
    int row0 = blockIdx.x * 128;
    int el = tid >> 2, cg = (tid & 3) << 5;
    int rg = min(row0 + el, NN - 1);

    if (tid < C) {
        s_vec[tid] = nb1[tid];
        s_vec[C + tid] = nb2[tid];
        if (DEC) { s_vec[2 * C + tid] = lg[tid]; s_vec[3 * C + tid] = lb[tid]; }
        s_mu[tid] = 0.f; s_s2[tid] = 0.f;
    }
    for (int idx = tid; idx < C * C; idx += 512) {
        int n = idx >> 7, k = idx & 127;
        uint32_t o = (uint32_t)(n * ASTB + k * 2);
        st_wsplit(smem, N_BAH, N_BAL, o, nw1[k * C + n]);
        st_wsplit(smem, N_BBH, N_BBL, o, nw1[(C + k) * C + n]);
    }
    {
        const float4* pa = (const float4*)(h + (size_t)rg * C + cg);
#pragma unroll
        for (int qq = 0; qq < 8; qq++) {
            float4 a = pa[qq];
            int c = cg + qq * 4;
            st_split(smem, N_AHI, N_ALO, el, c, a.x, a.y);
            st_split(smem, N_AHI, N_ALO, el, c + 2, a.z, a.w);
        }
    }
    __syncthreads();

    float acc[8][4];
    zero_acc(acc);
    mma_pass(acc, sb, N_AHI, N_BAH, wm, wn, lane);
    mma_pass(acc, sb, N_AHI, N_BAL, wm, wn, lane);
    mma_pass(acc, sb, N_ALO, N_BAH, wm, wn, lane);
    __syncthreads();
    {
        const float4* pa = (const float4*)(hagg + (size_t)rg * C + cg);
#pragma unroll
        for (int qq = 0; qq < 8; qq++) {
            float4 a = pa[qq];
            int c = cg + qq * 4;
            st_split(smem, N_AHI, N_ALO, el, c, a.x, a.y);
            st_split(smem, N_AHI, N_ALO, el, c + 2, a.z, a.w);
        }
    }
    __syncthreads();
    mma_pass(acc, sb, N_AHI, N_BBH, wm, wn, lane);
    mma_pass(acc, sb, N_AHI, N_BBL, wm, wn, lane);
    mma_pass(acc, sb, N_ALO, N_BBH, wm, wn, lane);
    __syncthreads();
    int r0 = wm * 16 + g, r1 = r0 + 8;
#pragma unroll
    for (int j = 0; j < 8; j++) {
        int col = wn * 64 + j * 8 + q4 * 2;
        float b0 = s_vec[col], b1 = s_vec[col + 1];
        st_split(smem, N_AHI, N_ALO, r0, col, silu_f(acc[j][0] + b0), silu_f(acc[j][1] + b1));
        st_split(smem, N_AHI, N_ALO, r1, col, silu_f(acc[j][2] + b0), silu_f(acc[j][3] + b1));
    }
    for (int idx = tid; idx < C * C; idx += 512) {
        int n = idx >> 7, k = idx & 127;
        uint32_t o = (uint32_t)(n * ASTB + k * 2);
        st_wsplit(smem, N_BAH, N_BAL, o, nw2[k * C + n]);
    }
    __syncthreads();
    zero_acc(acc);
    mma_pass(acc, sb, N_AHI, N_BAH, wm, wn, lane);
    mma_pass(acc, sb, N_AHI, N_BAL, wm, wn, lane);
    mma_pass(acc, sb, N_ALO, N_BAH, wm, wn, lane);
    bool v0 = (row0 + r0) < NN, v1 = (row0 + r1) < NN;
    if (!DEC) {
#pragma unroll
        for (int j = 0; j < 8; j++) {
            int col = wn * 64 + j * 8 + q4 * 2;
            float b0 = s_vec[C + col], b1 = s_vec[C + col + 1];
            if (v0) { out[(size_t)(row0 + r0) * C + col] = acc[j][0] + b0; out[(size_t)(row0 + r0) * C + col + 1] = acc[j][1] + b1; }
            if (v1) { out[(size_t)(row0 + r1) * C + col] = acc[j][2] + b0; out[(size_t)(row0 + r1) * C + col + 1] = acc[j][3] + b1; }
        }
    } else {
        float s0 = 0.f, q0 = 0.f, s1 = 0.f, q1 = 0.f;
#pragma unroll
        for (int j = 0; j < 8; j++) {
            int col = wn * 64 + j * 8 + q4 * 2;
            float b0 = s_vec[C + col], b1 = s_vec[C + col + 1];
            float x00 = gelu_f(acc[j][0] + b0), x01 = gelu_f(acc[j][1] + b1);
            float x10 = gelu_f(acc[j][2] + b0), x11 = gelu_f(acc[j][3] + b1);
            acc[j][0] = x00; acc[j][1] = x01; acc[j][2] = x10; acc[j][3] = x11;
            s0 += x00 + x01; q0 += x00 * x00 + x01 * x01;
            s1 += x10 + x11; q1 += x10 * x10 + x11 * x11;
        }
        atomicAdd(&s_mu[r0], s0); atomicAdd(&s_s2[r0], q0);
        atomicAdd(&s_mu[r1], s1); atomicAdd(&s_s2[r1], q1);
        __syncthreads();
        float mu0 = s_mu[r0] * (1.f / C), var0 = s_s2[r0] * (1.f / C) - mu0 * mu0;
        float mu1 = s_mu[r1] * (1.f / C), var1 = s_s2[r1] * (1.f / C) - mu1 * mu1;
        float is0 = rsqrtf(var0 + 1e-5f), is1 = rsqrtf(var1 + 1e-5f);
#pragma unroll
        for (int j = 0; j < 8; j++) {
            int col = wn * 64 + j * 8 + q4 * 2;
            float g0 = s_vec[2 * C + col], g1 = s_vec[2 * C + col + 1];
            float bb0 = s_vec[3 * C + col], bb1 = s_vec[3 * C + col + 1];
            if (v0) {
                out[(size_t)(row0 + r0) * C + col] = (acc[j][0] - mu0) * is0 * g0 + bb0;
                out[(size_t)(row0 + r0) * C + col + 1] = (acc[j][1] - mu0) * is0 * g1 + bb1;
            }
            if (v1) {
                out[(size_t)(row0 + r1) * C + col] = (acc[j][2] - mu1) * is1 * g0 + bb0;
                out[(size_t)(row0 + r1) * C + col + 1] = (acc[j][3] - mu1) * is1 * g1 + bb1;
            }
        }
    }
}

// ---------------- remaining scalar kernels ----------------
__device__ __forceinline__ float2 blk_red2_128(float v1, float v2, float* s) {
    int lane = threadIdx.x & 31, w = threadIdx.x >> 5;
#pragma unroll
    for (int o = 16; o > 0; o >>= 1) {
        v1 += __shfl_down_sync(0xffffffffu, v1, o);
        v2 += __shfl_down_sync(0xffffffffu, v2, o);
    }
    if (lane == 0) { s[w] = v1; s[4 + w] = v2; }
    __syncthreads();
    float2 r = make_float2(s[0] + s[1] + s[2] + s[3], s[4] + s[5] + s[6] + s[7]);
    __syncthreads();
    return r;
}

template <int K>
__global__ __launch_bounds__(128) void embed_kernel(
    const float* __restrict__ in, const float* __restrict__ W, const float* __restrict__ b,
    const float* __restrict__ lg, const float* __restrict__ lb, float* __restrict__ out)
{
    const int R = 4;
    __shared__ float s_in[R * K];
    __shared__ float s_red[8];
    int tid = threadIdx.x;
    int row0 = blockIdx.x * R;
    for (int i = tid; i < R * K; i += 128) s_in[i] = in[row0 * K + i];
    __syncthreads();
    float acc[R];
#pragma unroll
    for (int r = 0; r < R; r++) acc[r] = b[tid];
    for (int k = 0; k < K; k++) {
        float w = W[k * C + tid];
#pragma unroll
        for (int r = 0; r < R; r++) acc[r] += s_in[r * K + k] * w;
    }
    float gg = lg[tid], bb = lb[tid];
#pragma unroll
    for (int r = 0; r < R; r++) {
        float2 sv = blk_red2_128(acc[r], acc[r] * acc[r], s_red);
        float mu = sv.x * (1.f / C);
        float var = sv.y * (1.f / C) - mu * mu;
        float y = (acc[r] - mu) * rsqrtf(var + 1e-5f) * gg + bb;
        out[(row0 + r) * C + tid] = gelu_f(y);
    }
}

__global__ void coord_add_kernel(const float* __restrict__ xyz, const float* __restrict__ xagg,
                                 float* __restrict__ coord)
{
    int i = blockIdx.x * 256 + threadIdx.x;
    if (i < NN * 3) coord[i] = xyz[i] + xagg[i];
}

__global__ __launch_bounds__(256) void out_kernel(
    const float* __restrict__ h, const float* __restrict__ W,
    const float* __restrict__ b, float* __restrict__ out)
{
    int n = blockIdx.x * 8 + (threadIdx.x >> 5);
    if (n >= NN) return;
    int lane = threadIdx.x & 31;
    float a0 = 0.f, a1 = 0.f, a2 = 0.f;
#pragma unroll
    for (int q = 0; q < 4; q++) {
        int k = lane + 32 * q;
        float x = h[(size_t)n * C + k];
        a0 += x * W[k * 3 + 0]; a1 += x * W[k * 3 + 1]; a2 += x * W[k * 3 + 2];
    }
#pragma unroll
    for (int o = 16; o > 0; o >>= 1) {
        a0 += __shfl_down_sync(0xffffffffu, a0, o);
        a1 += __shfl_down_sync(0xffffffffu, a1, o);
        a2 += __shfl_down_sync(0xffffffffu, a2, o);
    }
    if (lane == 0) {
        out[n * 3 + 0] = a0 + b[0];
        out[n * 3 + 1] = a1 + b[1];
        out[n * 3 + 2] = a2 + b[2];
    }
}

extern "C" void kernel_launch(void* const* d_in, const int* in_sizes, int n_in,
                              void* d_out, int out_size)
{
    const int*   src       = (const int*)d_in[0];
    const int*   dst       = (const int*)d_in[1];
    const float* node_attr = (const float*)d_in[2];
    const float* xyz       = (const float*)d_in[3];
    const float* emb_w1    = (const float*)d_in[4];
    const float* emb_b1    = (const float*)d_in[5];
    const float* ln1_g     = (const float*)d_in[6];
    const float* ln1_b     = (const float*)d_in[7];
    const float* emb_w2    = (const float*)d_in[8];
    const float* emb_b2    = (const float*)d_in[9];
    const float* ln2_g     = (const float*)d_in[10];
    const float* ln2_b     = (const float*)d_in[11];
    const float* e_w1      = (const float*)d_in[12];
    const float* e_b1      = (const float*)d_in[13];
    const float* e_w2      = (const float*)d_in[14];
    const float* e_b2      = (const float*)d_in[15];
    const float* n_w1      = (const float*)d_in[16];
    const float* n_b1      = (const float*)d_in[17];
    const float* n_w2      = (const float*)d_in[18];
    const float* n_b2      = (const float*)d_in[19];
    const float* c_w1      = (const float*)d_in[20];
    const float* c_b1      = (const float*)d_in[21];
    const float* c_w2      = (const float*)d_in[22];
    const float* dec_ln_g  = (const float*)d_in[23];
    const float* dec_ln_b  = (const float*)d_in[24];
    const float* out_w     = (const float*)d_in[25];
    const float* out_b     = (const float*)d_in[26];
    float* out = (float*)d_out;

    float *h, *hn, *hs, *hd, *hagg, *xagg, *coord;
    cudaGetSymbolAddress((void**)&h, g_h);
    cudaGetSymbolAddress((void**)&hn, g_hn);
    cudaGetSymbolAddress((void**)&hs, g_hs);
    cudaGetSymbolAddress((void**)&hd, g_hd);
    cudaGetSymbolAddress((void**)&hagg, g_hagg);
    cudaGetSymbolAddress((void**)&xagg, g_xagg);
    cudaGetSymbolAddress((void**)&coord, g_coord);

    int dev = 0;
    cudaGetDevice(&dev);
    int nsm = 148;
    cudaDeviceGetAttribute(&nsm, cudaDevAttrMultiProcessorCount, dev);

    cudaFuncSetAttribute((const void*)edge_nc_kernel,
                         cudaFuncAttributeMaxDynamicSharedMemorySize, SMEM_NC);
    cudaFuncSetAttribute((const void*)edge_co_kernel,
                         cudaFuncAttributeMaxDynamicSharedMemorySize, SMEM_EDGE_CO);
    cudaFuncSetAttribute((const void*)pre_mma_kernel,
                         cudaFuncAttributeMaxDynamicSharedMemorySize, SMEM_PRE);
    cudaFuncSetAttribute((const void*)node_mma_kernel<false>,
                         cudaFuncAttributeMaxDynamicSharedMemorySize, SMEM_NODE);
    cudaFuncSetAttribute((const void*)node_mma_kernel<true>,
                         cudaFuncAttributeMaxDynamicSharedMemorySize, SMEM_NODE);

    embed_kernel<64><<<NN / 4, 128>>>(node_attr, emb_w1, emb_b1, ln1_g, ln1_b, hn);
    embed_kernel<128><<<NN / 4, 128>>>(hn, emb_w2, emb_b2, ln2_g, ln2_b, h);

    float* hcur = h;
    float* htmp = hn;
    for (int l = 0; l < 3; l++) {
        const float* ew1l = e_w1 + (size_t)l * 257 * C;
        pre_mma_kernel<<<NROWT, 512, SMEM_PRE>>>(hcur, ew1l, hs, hd);
        cudaMemsetAsync(hagg, 0, (size_t)NN * C * sizeof(float));
        const float* Xl = (l == 2) ? coord : xyz;
        if (l == 1) {
            cudaMemsetAsync(xagg, 0, (size_t)NN * 3 * sizeof(float));
            edge_co_kernel<<<nsm, 512, SMEM_EDGE_CO>>>(
                src, dst, Xl, hs, hd, ew1l + 256 * C, e_b1 + l * C,
                e_w2 + (size_t)l * C * C, e_b2 + l * C,
                c_w1 + (size_t)l * C * C, c_b1 + l * C, c_w2 + l * C, hagg, xagg);
        } else {
            edge_nc_kernel<<<nsm * 2, 256, SMEM_NC>>>(
                src, dst, Xl, hs, hd, ew1l + 256 * C, e_b1 + l * C,
                e_w2 + (size_t)l * C * C, e_b2 + l * C, hagg);
        }
        if (l == 0)
            node_mma_kernel<false><<<NROWT, 512, SMEM_NODE>>>(hcur, hagg,
                n_w1 + (size_t)l * 256 * C, n_b1 + l * C,
                n_w2 + (size_t)l * C * C, n_b2 + l * C, dec_ln_g, dec_ln_b, htmp);
        else
            node_mma_kernel<true><<<NROWT, 512, SMEM_NODE>>>(hcur, hagg,
                n_w1 + (size_t)l * 256 * C, n_b1 + l * C,
                n_w2 + (size_t)l * C * C, n_b2 + l * C, dec_ln_g, dec_ln_b, htmp);
        float* t = hcur; hcur = htmp; htmp = t;
        if (l == 1) coord_add_kernel<<<(NN * 3 + 255) / 256, 256>>>(xyz, xagg, coord);
    }
    out_kernel<<<(NN + 7) / 8, 256>>>(hcur, out_w, out_b, out);
}

// round 12
// speedup vs baseline: 1.2518x; 1.2518x over previous
#include <cuda_runtime.h>
#include <cuda_bf16.h>
#include <math.h>
#include <stdint.h>

#define NN 50000
#define NE 1600000
#define C 128
#define ETILE 128
#define NTILES (NE / ETILE)
#define NROWT ((NN + 127) / 128)
#define AST 136
#define ASTB (AST * 2)
#define FST 132              // fp32 tf32 tile row stride (floats)

// ---------------- scratch ----------------
__device__ float g_h[NN * C];
__device__ float g_hn[NN * C];
__device__ float g_hs[NN * C];
__device__ float g_hd[NN * C];
__device__ float g_hagg[NN * C];
__device__ float g_xagg[NN * 3];
__device__ float g_coord[NN * 3];

__device__ __forceinline__ float silu_f(float x) { return x * (1.f / (1.f + __expf(-x))); }
__device__ __forceinline__ float gelu_f(float x) { return 0.5f * x * (1.f + erff(x * 0.70710678118654752f)); }

__device__ __forceinline__ void red2(float* a, float x, float y) {
    asm volatile("red.global.add.v2.f32 [%0], {%1,%2};" :: "l"(a), "f"(x), "f"(y) : "memory");
}
__device__ __forceinline__ uint32_t smem_u32(const void* p) {
    uint32_t a;
    asm("{ .reg .u64 t; cvta.to.shared.u64 t, %1; cvt.u32.u64 %0, t; }" : "=r"(a) : "l"(p));
    return a;
}
__device__ __forceinline__ uint32_t to_tf32(float x) {
    uint32_t r;
    asm("cvt.rna.tf32.f32 %0, %1;" : "=r"(r) : "f"(x));
    return r;
}
__device__ __forceinline__ void mma_tf32(float* c, uint32_t a0, uint32_t a1, uint32_t a2, uint32_t a3,
                                         uint32_t b0, uint32_t b1) {
    asm volatile("mma.sync.aligned.m16n8k8.row.col.f32.tf32.tf32.f32 "
                 "{%0,%1,%2,%3},{%4,%5,%6,%7},{%8,%9},{%0,%1,%2,%3};"
                 : "+f"(c[0]), "+f"(c[1]), "+f"(c[2]), "+f"(c[3])
                 : "r"(a0), "r"(a1), "r"(a2), "r"(a3), "r"(b0), "r"(b1));
}
// ---- bf16 helpers (pre/node kernels, proven) ----
__device__ __forceinline__ void ldm_x4(uint32_t& r0, uint32_t& r1, uint32_t& r2, uint32_t& r3, uint32_t addr) {
    asm volatile("ldmatrix.sync.aligned.m8n8.x4.shared.b16 {%0,%1,%2,%3}, [%4];"
                 : "=r"(r0), "=r"(r1), "=r"(r2), "=r"(r3) : "r"(addr));
}
__device__ __forceinline__ void mma_bf16(float* c, uint32_t a0, uint32_t a1, uint32_t a2, uint32_t a3,
                                         uint32_t b0, uint32_t b1) {
    asm volatile("mma.sync.aligned.m16n8k16.row.col.f32.bf16.bf16.f32 "
                 "{%0,%1,%2,%3},{%4,%5,%6,%7},{%8,%9},{%0,%1,%2,%3};"
                 : "+f"(c[0]), "+f"(c[1]), "+f"(c[2]), "+f"(c[3])
                 : "r"(a0), "r"(a1), "r"(a2), "r"(a3), "r"(b0), "r"(b1));
}
__device__ __forceinline__ void st_split(char* smem, uint32_t offH, uint32_t offL,
                                         int r, int c, float v0, float v1) {
    uint32_t o = (uint32_t)(r * ASTB + c * 2);
    __nv_bfloat162 hi, lo;
    hi.x = __float2bfloat16(v0);
    hi.y = __float2bfloat16(v1);
    lo.x = __float2bfloat16(v0 - __bfloat162float(hi.x));
    lo.y = __float2bfloat16(v1 - __bfloat162float(hi.y));
    *(__nv_bfloat162*)(smem + offH + o) = hi;
    *(__nv_bfloat162*)(smem + offL + o) = lo;
}
__device__ __forceinline__ void st_wsplit(char* smem, uint32_t offH, uint32_t offL, uint32_t o, float w) {
    __nv_bfloat16 h1 = __float2bfloat16(w);
    *(__nv_bfloat16*)(smem + offH + o) = h1;
    *(__nv_bfloat16*)(smem + offL + o) = __float2bfloat16(w - __bfloat162float(h1));
}
__device__ __forceinline__ void mma_pass(float acc[8][4], uint32_t sb, uint32_t aoff, uint32_t boff,
                                         int wm, int wn, int lane) {
    uint32_t a_base = sb + aoff + (uint32_t)((wm * 16 + (lane & 15)) * ASTB + ((lane >> 4) << 3) * 2);
    uint32_t b_base = sb + boff + (uint32_t)((wn * 64 + ((lane >> 4) << 3) + (lane & 7)) * ASTB
                                             + (((lane >> 3) & 1) << 3) * 2);
#pragma unroll
    for (int k8 = 0; k8 < 8; k8++) {
        uint32_t a0, a1, a2, a3;
        ldm_x4(a0, a1, a2, a3, a_base + k8 * 32);
#pragma unroll
        for (int j4 = 0; j4 < 4; j4++) {
            uint32_t b0, b1, b2, b3;
            ldm_x4(b0, b1, b2, b3, b_base + (uint32_t)(j4 * 16 * ASTB) + k8 * 32);
            mma_bf16(acc[2 * j4], a0, a1, a2, a3, b0, b1);
            mma_bf16(acc[2 * j4 + 1], a0, a1, a2, a3, b2, b3);
        }
    }
}
__device__ __forceinline__ void zero_acc(float acc[8][4]) {
#pragma unroll
    for (int j = 0; j < 8; j++) { acc[j][0] = acc[j][1] = acc[j][2] = acc[j][3] = 0.f; }
}

// tf32 m16n64 GEMM over K=128: A fp32-tile [128][FST], B interleaved pairs [64][FST float2]
__device__ __forceinline__ void mma_tf32_pass(float acc[8][4], const uint32_t* As, const uint2* Bt,
                                              int wm, int wn, int g, int q4) {
    int r0 = (wm * 16 + g) * FST, r1 = r0 + 8 * FST;
    int nj = wn * 64 + g;
#pragma unroll
    for (int s = 0; s < 16; s++) {
        int k0 = 8 * s + q4;
        uint32_t a0 = As[r0 + k0], a1 = As[r1 + k0];
        uint32_t a2 = As[r0 + k0 + 4], a3 = As[r1 + k0 + 4];
        int p = (s * 4 + q4) * FST + nj;
#pragma unroll
        for (int j = 0; j < 8; j++) {
            uint2 b = Bt[p + j * 8];
            mma_tf32(acc[j], a0, a1, a2, a3, b.x, b.y);
        }
    }
}

// build interleaved B: Bt[p][n] = (tf32 W[k0][n], tf32 W[k0+4][n]), p=(s*4+q), k0=8s+q
template <int NT>
__device__ __forceinline__ void build_bt(uint2* Bt, const float* W, int tid) {
    for (int idx = tid; idx < 64 * C; idx += NT) {
        int p = idx >> 7, n = idx & 127;
        int k0 = ((p >> 2) << 3) + (p & 3);
        Bt[p * FST + n] = make_uint2(to_tf32(W[k0 * C + n]), to_tf32(W[(k0 + 4) * C + n]));
    }
}

#define TILE_B   (128 * ASTB)          // bf16 tile bytes (pre/node)
#define TILE_F   (128 * FST * 4)       // fp32 tf32 A tile bytes = 67584
#define TILE_BT  (64 * FST * 8)        // interleaved B bytes = 67584

// ---- NC edge kernel smem (tf32): vec | A0 | A1 | BT ----
#define NC_VEC 0
#define NC_A0  2048
#define NC_A1  (NC_A0 + TILE_F)
#define NC_BT  (NC_A1 + TILE_F)
#define SMEM_NCT (NC_BT + TILE_BT)     // 204800

// ---- CO edge kernel smem (tf32): vec | geo | cm | A | BT1 | BT2 ----
#define CV_VEC 0
#define CV_GEO 2560
#define CV_CM  4608
#define CV_A   5120
#define CV_BT1 (CV_A + TILE_F)
#define CV_BT2 (CV_BT1 + TILE_BT)
#define SMEM_COT (CV_BT2 + TILE_BT)    // 207872

// ---------------- NC edge kernel: tf32 1-pass, double-buffered A, 1 bar/tile ----------------
__global__ __launch_bounds__(512, 1) void edge_nc_kernel(
    const int* __restrict__ src, const int* __restrict__ dst,
    const float* __restrict__ X,
    const float* __restrict__ hs, const float* __restrict__ hd,
    const float* __restrict__ wr, const float* __restrict__ eb1,
    const float* __restrict__ ew2, const float* __restrict__ eb2,
    float* __restrict__ hagg)
{
    extern __shared__ char smem[];
    float* s_vec = (float*)(smem + NC_VEC);
    int tid = threadIdx.x, warp = tid >> 5, lane = tid & 31;
    int wm = warp >> 1, wn = warp & 1;
    int g = lane >> 2, q4 = lane & 3;

    if (tid < C) {
        s_vec[tid] = wr[tid];
        s_vec[C + tid] = eb1[tid];
        s_vec[2 * C + tid] = eb2[tid];
    }
    build_bt<512>((uint2*)(smem + NC_BT), ew2, tid);
    __syncthreads();

    int el = tid >> 2, cg = (tid & 3) << 5;
    const uint2* Bt = (const uint2*)(smem + NC_BT);
    int par = 0;

    for (int tile = blockIdx.x; tile < NTILES; tile += gridDim.x, par ^= 1) {
        uint32_t aoff = par ? NC_A1 : NC_A0;
        // ---- m1 = silu(hs[src] + hd[dst] + rad*wr + eb1) -> A (tf32) ----
        {
            int e = tile * ETILE + el;
            int si = src[e], di = dst[e];
            float ax = X[si * 3 + 0] - X[di * 3 + 0];
            float ay = X[si * 3 + 1] - X[di * 3 + 1];
            float az = X[si * 3 + 2] - X[di * 3 + 2];
            float rad = ax * ax + ay * ay + az * az;
            const float4* ps = (const float4*)(hs + (size_t)si * C + cg);
            const float4* pd = (const float4*)(hd + (size_t)di * C + cg);
#pragma unroll
            for (int qq = 0; qq < 8; qq++) {
                float4 a = ps[qq], b = pd[qq];
                int c = cg + qq * 4;
                uint4 pk;
                pk.x = to_tf32(silu_f(a.x + b.x + rad * s_vec[c + 0] + s_vec[C + c + 0]));
                pk.y = to_tf32(silu_f(a.y + b.y + rad * s_vec[c + 1] + s_vec[C + c + 1]));
                pk.z = to_tf32(silu_f(a.z + b.z + rad * s_vec[c + 2] + s_vec[C + c + 2]));
                pk.w = to_tf32(silu_f(a.w + b.w + rad * s_vec[c + 3] + s_vec[C + c + 3]));
                *(uint4*)(smem + aoff + (uint32_t)(el * FST + c) * 4) = pk;
            }
        }
        __syncthreads();
        // ---- MMA: D = m1 @ ew2 (tf32 single pass) ----
        float acc[8][4];
        zero_acc(acc);
        mma_tf32_pass(acc, (const uint32_t*)(smem + aoff), Bt, wm, wn, g, q4);
        // ---- epilogue: m2 = silu(D + eb2) -> hagg atomics (no barrier; A double-buffered) ----
        {
            int r0 = wm * 16 + g, r1 = r0 + 8;
            int d0 = dst[tile * ETILE + r0], d1 = dst[tile * ETILE + r1];
            float* h0 = hagg + (size_t)d0 * C;
            float* h1 = hagg + (size_t)d1 * C;
#pragma unroll
            for (int j = 0; j < 8; j++) {
                int col = wn * 64 + j * 8 + q4 * 2;
                float b0 = s_vec[2 * C + col], b1 = s_vec[2 * C + col + 1];
                red2(h0 + col, silu_f(acc[j][0] + b0), silu_f(acc[j][1] + b1));
                red2(h1 + col, silu_f(acc[j][2] + b0), silu_f(acc[j][3] + b1));
            }
        }
    }
}

// ---------------- CO edge kernel: tf32 1-pass both GEMMs ----------------
__global__ __launch_bounds__(512, 1) void edge_co_kernel(
    const int* __restrict__ src, const int* __restrict__ dst,
    const float* __restrict__ X,
    const float* __restrict__ hs, const float* __restrict__ hd,
    const float* __restrict__ wr, const float* __restrict__ eb1,
    const float* __restrict__ ew2, const float* __restrict__ eb2,
    const float* __restrict__ cw1, const float* __restrict__ cb1,
    const float* __restrict__ cw2,
    float* __restrict__ hagg, float* __restrict__ xagg)
{
    extern __shared__ char smem[];
    float* s_vec = (float*)(smem + CV_VEC);
    float4* s_geo = (float4*)(smem + CV_GEO);
    float* s_cm = (float*)(smem + CV_CM);
    int tid = threadIdx.x, warp = tid >> 5, lane = tid & 31;
    int wm = warp >> 1, wn = warp & 1;
    int g = lane >> 2, q4 = lane & 3;

    if (tid < C) {
        s_vec[tid] = wr[tid];
        s_vec[C + tid] = eb1[tid];
        s_vec[2 * C + tid] = eb2[tid];
        s_vec[3 * C + tid] = cb1[tid];
        s_vec[4 * C + tid] = cw2[tid];
    }
    if (tid < ETILE) s_cm[tid] = 0.f;
    build_bt<512>((uint2*)(smem + CV_BT1), ew2, tid);
    build_bt<512>((uint2*)(smem + CV_BT2), cw1, tid);
    __syncthreads();

    int el = tid >> 2, cg = (tid & 3) << 5;
    const uint2* Bt1 = (const uint2*)(smem + CV_BT1);
    const uint2* Bt2 = (const uint2*)(smem + CV_BT2);
    const uint32_t* As = (const uint32_t*)(smem + CV_A);

    for (int tile = blockIdx.x; tile < NTILES; tile += gridDim.x) {
        // ---- m1 -> A (tf32) ----
        {
            int e = tile * ETILE + el;
            int si = src[e], di = dst[e];
            float ax = X[si * 3 + 0] - X[di * 3 + 0];
            float ay = X[si * 3 + 1] - X[di * 3 + 1];
            float az = X[si * 3 + 2] - X[di * 3 + 2];
            float rad = ax * ax + ay * ay + az * az;
            if ((tid & 3) == 0)
                s_geo[el] = make_float4(ax, ay, az, 1.f / (sqrtf(rad) + 1e-30f));
            const float4* ps = (const float4*)(hs + (size_t)si * C + cg);
            const float4* pd = (const float4*)(hd + (size_t)di * C + cg);
#pragma unroll
            for (int qq = 0; qq < 8; qq++) {
                float4 a = ps[qq], b = pd[qq];
                int c = cg + qq * 4;
                uint4 pk;
                pk.x = to_tf32(silu_f(a.x + b.x + rad * s_vec[c + 0] + s_vec[C + c + 0]));
                pk.y = to_tf32(silu_f(a.y + b.y + rad * s_vec[c + 1] + s_vec[C + c + 1]));
                pk.z = to_tf32(silu_f(a.z + b.z + rad * s_vec[c + 2] + s_vec[C + c + 2]));
                pk.w = to_tf32(silu_f(a.w + b.w + rad * s_vec[c + 3] + s_vec[C + c + 3]));
                *(uint4*)(smem + CV_A + (uint32_t)(el * FST + c) * 4) = pk;
            }
        }
        __syncthreads();
        // ---- MMA1: D1 = m1 @ ew2 ----
        float acc[8][4];
        zero_acc(acc);
        mma_tf32_pass(acc, As, Bt1, wm, wn, g, q4);
        __syncthreads();   // all warps done reading A before restage
        // ---- restage m2 = silu(D1 + eb2) into A (tf32) + hagg atomics ----
        {
            int r0 = wm * 16 + g, r1 = r0 + 8;
            int d0 = dst[tile * ETILE + r0], d1 = dst[tile * ETILE + r1];
            float* h0 = hagg + (size_t)d0 * C;
            float* h1 = hagg + (size_t)d1 * C;
#pragma unroll
            for (int j = 0; j < 8; j++) {
                int col = wn * 64 + j * 8 + q4 * 2;
                float b0 = s_vec[2 * C + col], b1 = s_vec[2 * C + col + 1];
                float m00 = silu_f(acc[j][0] + b0), m01 = silu_f(acc[j][1] + b1);
                float m10 = silu_f(acc[j][2] + b0), m11 = silu_f(acc[j][3] + b1);
                red2(h0 + col, m00, m01);
                red2(h1 + col, m10, m11);
                *(uint2*)(smem + CV_A + (uint32_t)(r0 * FST + col) * 4) = make_uint2(to_tf32(m00), to_tf32(m01));
                *(uint2*)(smem + CV_A + (uint32_t)(r1 * FST + col) * 4) = make_uint2(to_tf32(m10), to_tf32(m11));
            }
        }
        __syncthreads();
        // ---- MMA2: D2 = m2 @ cw1 ----
        zero_acc(acc);
        mma_tf32_pass(acc, As, Bt2, wm, wn, g, q4);
        // ---- cm = sum_c silu(D2 + cb1) * cw2 ----
        {
            float p0 = 0.f, p1 = 0.f;
#pragma unroll
            for (int j = 0; j < 8; j++) {
                int col = wn * 64 + j * 8 + q4 * 2;
                float cb0 = s_vec[3 * C + col], cb1v = s_vec[3 * C + col + 1];
                float w0 = s_vec[4 * C + col], w1 = s_vec[4 * C + col + 1];
                p0 += silu_f(acc[j][0] + cb0) * w0 + silu_f(acc[j][1] + cb1v) * w1;
                p1 += silu_f(acc[j][2] + cb0) * w0 + silu_f(acc[j][3] + cb1v) * w1;
            }
            int r0 = wm * 16 + g;
            atomicAdd(&s_cm[r0], p0);
            atomicAdd(&s_cm[r0 + 8], p1);
        }
        __syncthreads();
        if (tid < ETILE) {
            float cm = s_cm[tid];
            s_cm[tid] = 0.f;
            float4 gg = s_geo[tid];
            int d2 = dst[tile * ETILE + tid];
            float s = cm * gg.w;
            atomicAdd(&xagg[d2 * 3 + 0], s * gg.x);
            atomicAdd(&xagg[d2 * 3 + 1], s * gg.y);
            atomicAdd(&xagg[d2 * 3 + 2], s * gg.z);
        }
        __syncthreads();
    }
}

// ================= tensorized node-side kernels (R7, passing, bf16 3-pass) =================
#define P_AHI 0
#define P_ALO (P_AHI + TILE_B)
#define P_SH  (P_ALO + TILE_B)
#define P_SL  (P_SH + TILE_B)
#define P_DH  (P_SL + TILE_B)
#define P_DL  (P_DH + TILE_B)
#define SMEM_PRE (P_DL + TILE_B)

__global__ __launch_bounds__(512, 1) void pre_mma_kernel(
    const float* __restrict__ h, const float* __restrict__ ew1,
    float* __restrict__ hs, float* __restrict__ hd)
{
    extern __shared__ char smem[];
    uint32_t sb = smem_u32(smem);
    int tid = threadIdx.x, warp = tid >> 5, lane = tid & 31;
    int wm = warp >> 1, wn = warp & 1, g = lane >> 2, q4 = lane & 3;
    int row0 = blockIdx.x * 128;

    for (int idx = tid; idx < C * C; idx += 512) {
        int n = idx >> 7, k = idx & 127;
        uint32_t o = (uint32_t)(n * ASTB + k * 2);
        st_wsplit(smem, P_SH, P_SL, o, ew1[k * C + n]);
        st_wsplit(smem, P_DH, P_DL, o, ew1[(C + k) * C + n]);
    }
    {
        int el = tid >> 2, cg = (tid & 3) << 5;
        int rg = min(row0 + el, NN - 1);
        const float4* pa = (const float4*)(h + (size_t)rg * C + cg);
#pragma unroll
        for (int qq = 0; qq < 8; qq++) {
            float4 a = pa[qq];
            int c = cg + qq * 4;
            st_split(smem, P_AHI, P_ALO, el, c, a.x, a.y);
            st_split(smem, P_AHI, P_ALO, el, c + 2, a.z, a.w);
        }
    }
    __syncthreads();

    int r0 = wm * 16 + g, r1 = r0 + 8;
    bool v0 = (row0 + r0) < NN, v1 = (row0 + r1) < NN;
    float acc[8][4];

    zero_acc(acc);
    mma_pass(acc, sb, P_AHI, P_SH, wm, wn, lane);
    mma_pass(acc, sb, P_AHI, P_SL, wm, wn, lane);
    mma_pass(acc, sb, P_ALO, P_SH, wm, wn, lane);
#pragma unroll
    for (int j = 0; j < 8; j++) {
        int col = wn * 64 + j * 8 + q4 * 2;
        if (v0) { hs[(size_t)(row0 + r0) * C + col] = acc[j][0]; hs[(size_t)(row0 + r0) * C + col + 1] = acc[j][1]; }
        if (v1) { hs[(size_t)(row0 + r1) * C + col] = acc[j][2]; hs[(size_t)(row0 + r1) * C + col + 1] = acc[j][3]; }
    }
    zero_acc(acc);
    mma_pass(acc, sb, P_AHI, P_DH, wm, wn, lane);
    mma_pass(acc, sb, P_AHI, P_DL, wm, wn, lane);
    mma_pass(acc, sb, P_ALO, P_DH, wm, wn, lane);
#pragma unroll
    for (int j = 0; j < 8; j++) {
        int col = wn * 64 + j * 8 + q4 * 2;
        if (v0) { hd[(size_t)(row0 + r0) * C + col] = acc[j][0]; hd[(size_t)(row0 + r0) * C + col + 1] = acc[j][1]; }
        if (v1) { hd[(size_t)(row0 + r1) * C + col] = acc[j][2]; hd[(size_t)(row0 + r1) * C + col + 1] = acc[j][3]; }
    }
}

#define N_VEC  0
#define N_MU   2048
#define N_S2   2560
#define N_AHI  4096
#define N_ALO  (N_AHI + TILE_B)
#define N_BAH  (N_ALO + TILE_B)
#define N_BAL  (N_BAH + TILE_B)
#define N_BBH  (N_BAL + TILE_B)
#define N_BBL  (N_BBH + TILE_B)
#define SMEM_NODE (N_BBL + TILE_B)

template <bool DEC>
__global__ __launch_bounds__(512, 1) void node_mma_kernel(
    const float* __restrict__ h, const float* __restrict__ hagg,
    const float* __restrict__ nw1, const float* __restrict__ nb1,
    const float* __restrict__ nw2, const float* __restrict__ nb2,
    const float* __restrict__ lg, const float* __restrict__ lb,
    float* __restrict__ out)
{
    extern __shared__ char smem[];
    uint32_t sb = smem_u32(smem);
    float* s_vec = (float*)(smem + N_VEC);
    float* s_mu = (float*)(smem + N_MU);
    float* s_s2 = (float*)(smem + N_S2);
    int tid = threadIdx.x, warp = tid >> 5, lane = tid & 31;
    int wm = warp >> 1, wn = warp & 1, g = lane >> 2, q4 = lane & 3;
    int row0 = blockIdx.x * 128;
    int el = tid >> 2, cg = (tid & 3) << 5;
    int rg = min(row0 + el, NN - 1);

    if (tid < C) {
        s_vec[tid] = nb1[tid];
        s_vec[C + tid] = nb2[tid];
        if (DEC) { s_vec[2 * C + tid] = lg[tid]; s_vec[3 * C + tid] = lb[tid]; }
        s_mu[tid] = 0.f; s_s2[tid] = 0.f;
    }
    for (int idx = tid; idx < C * C; idx += 512) {
        int n = idx >> 7, k = idx & 127;
        uint32_t o = (uint32_t)(n * ASTB + k * 2);
        st_wsplit(smem, N_BAH, N_BAL, o, nw1[k * C + n]);
        st_wsplit(smem, N_BBH, N_BBL, o, nw1[(C + k) * C + n]);
    }
    {
        const float4* pa = (const float4*)(h + (size_t)rg * C + cg);
#pragma unroll
        for (int qq = 0; qq < 8; qq++) {
            float4 a = pa[qq];
            int c = cg + qq * 4;
            st_split(smem, N_AHI, N_ALO, el, c, a.x, a.y);
            st_split(smem, N_AHI, N_ALO, el, c + 2, a.z, a.w);
        }
    }
    __syncthreads();

    float acc[8][4];
    zero_acc(acc);
    mma_pass(acc, sb, N_AHI, N_BAH, wm, wn, lane);
    mma_pass(acc, sb, N_AHI, N_BAL, wm, wn, lane);
    mma_pass(acc, sb, N_ALO, N_BAH, wm, wn, lane);
    __syncthreads();
    {
        const float4* pa = (const float4*)(hagg + (size_t)rg * C + cg);
#pragma unroll
        for (int qq = 0; qq < 8; qq++) {
            float4 a = pa[qq];
            int c = cg + qq * 4;
            st_split(smem, N_AHI, N_ALO, el, c, a.x, a.y);
            st_split(smem, N_AHI, N_ALO, el, c + 2, a.z, a.w);
        }
    }
    __syncthreads();
    mma_pass(acc, sb, N_AHI, N_BBH, wm, wn, lane);
    mma_pass(acc, sb, N_AHI, N_BBL, wm, wn, lane);
    mma_pass(acc, sb, N_ALO, N_BBH, wm, wn, lane);
    __syncthreads();
    int r0 = wm * 16 + g, r1 = r0 + 8;
#pragma unroll
    for (int j = 0; j < 8; j++) {
        int col = wn * 64 + j * 8 + q4 * 2;
        float b0 = s_vec[col], b1 = s_vec[col + 1];
        st_split(smem, N_AHI, N_ALO, r0, col, silu_f(acc[j][0] + b0), silu_f(acc[j][1] + b1));
        st_split(smem, N_AHI, N_ALO, r1, col, silu_f(acc[j][2] + b0), silu_f(acc[j][3] + b1));
    }
    for (int idx = tid; idx < C * C; idx += 512) {
        int n = idx >> 7, k = idx & 127;
        uint32_t o = (uint32_t)(n * ASTB + k * 2);
        st_wsplit(smem, N_BAH, N_BAL, o, nw2[k * C + n]);
    }
    __syncthreads();
    zero_acc(acc);
    mma_pass(acc, sb, N_AHI, N_BAH, wm, wn, lane);
    mma_pass(acc, sb, N_AHI, N_BAL, wm, wn, lane);
    mma_pass(acc, sb, N_ALO, N_BAH, wm, wn, lane);
    bool v0 = (row0 + r0) < NN, v1 = (row0 + r1) < NN;
    if (!DEC) {
#pragma unroll
        for (int j = 0; j < 8; j++) {
            int col = wn * 64 + j * 8 + q4 * 2;
            float b0 = s_vec[C + col], b1 = s_vec[C + col + 1];
            if (v0) { out[(size_t)(row0 + r0) * C + col] = acc[j][0] + b0; out[(size_t)(row0 + r0) * C + col + 1] = acc[j][1] + b1; }
            if (v1) { out[(size_t)(row0 + r1) * C + col] = acc[j][2] + b0; out[(size_t)(row0 + r1) * C + col + 1] = acc[j][3] + b1; }
        }
    } else {
        float s0 = 0.f, q0 = 0.f, s1 = 0.f, q1 = 0.f;
#pragma unroll
        for (int j = 0; j < 8; j++) {
            int col = wn * 64 + j * 8 + q4 * 2;
            float b0 = s_vec[C + col], b1 = s_vec[C + col + 1];
            float x00 = gelu_f(acc[j][0] + b0), x01 = gelu_f(acc[j][1] + b1);
            float x10 = gelu_f(acc[j][2] + b0), x11 = gelu_f(acc[j][3] + b1);
            acc[j][0] = x00; acc[j][1] = x01; acc[j][2] = x10; acc[j][3] = x11;
            s0 += x00 + x01; q0 += x00 * x00 + x01 * x01;
            s1 += x10 + x11; q1 += x10 * x10 + x11 * x11;
        }
        atomicAdd(&s_mu[r0], s0); atomicAdd(&s_s2[r0], q0);
        atomicAdd(&s_mu[r1], s1); atomicAdd(&s_s2[r1], q1);
        __syncthreads();
        float mu0 = s_mu[r0] * (1.f / C), var0 = s_s2[r0] * (1.f / C) - mu0 * mu0;
        float mu1 = s_mu[r1] * (1.f / C), var1 = s_s2[r1] * (1.f / C) - mu1 * mu1;
        float is0 = rsqrtf(var0 + 1e-5f), is1 = rsqrtf(var1 + 1e-5f);
#pragma unroll
        for (int j = 0; j < 8; j++) {
            int col = wn * 64 + j * 8 + q4 * 2;
            float g0 = s_vec[2 * C + col], g1 = s_vec[2 * C + col + 1];
            float bb0 = s_vec[3 * C + col], bb1 = s_vec[3 * C + col + 1];
            if (v0) {
                out[(size_t)(row0 + r0) * C + col] = (acc[j][0] - mu0) * is0 * g0 + bb0;
                out[(size_t)(row0 + r0) * C + col + 1] = (acc[j][1] - mu0) * is0 * g1 + bb1;
            }
            if (v1) {
                out[(size_t)(row0 + r1) * C + col] = (acc[j][2] - mu1) * is1 * g0 + bb0;
                out[(size_t)(row0 + r1) * C + col + 1] = (acc[j][3] - mu1) * is1 * g1 + bb1;
            }
        }
    }
}

// ---------------- remaining scalar kernels ----------------
__device__ __forceinline__ float2 blk_red2_128(float v1, float v2, float* s) {
    int lane = threadIdx.x & 31, w = threadIdx.x >> 5;
#pragma unroll
    for (int o = 16; o > 0; o >>= 1) {
        v1 += __shfl_down_sync(0xffffffffu, v1, o);
        v2 += __shfl_down_sync(0xffffffffu, v2, o);
    }
    if (lane == 0) { s[w] = v1; s[4 + w] = v2; }
    __syncthreads();
    float2 r = make_float2(s[0] + s[1] + s[2] + s[3], s[4] + s[5] + s[6] + s[7]);
    __syncthreads();
    return r;
}

template <int K>
__global__ __launch_bounds__(128) void embed_kernel(
    const float* __restrict__ in, const float* __restrict__ W, const float* __restrict__ b,
    const float* __restrict__ lg, const float* __restrict__ lb, float* __restrict__ out)
{
    const int R = 4;
    __shared__ float s_in[R * K];
    __shared__ float s_red[8];
    int tid = threadIdx.x;
    int row0 = blockIdx.x * R;
    for (int i = tid; i < R * K; i += 128) s_in[i] = in[row0 * K + i];
    __syncthreads();
    float acc[R];
#pragma unroll
    for (int r = 0; r < R; r++) acc[r] = b[tid];
    for (int k = 0; k < K; k++) {
        float w = W[k * C + tid];
#pragma unroll
        for (int r = 0; r < R; r++) acc[r] += s_in[r * K + k] * w;
    }
    float gg = lg[tid], bb = lb[tid];
#pragma unroll
    for (int r = 0; r < R; r++) {
        float2 sv = blk_red2_128(acc[r], acc[r] * acc[r], s_red);
        float mu = sv.x * (1.f / C);
        float var = sv.y * (1.f / C) - mu * mu;
        float y = (acc[r] - mu) * rsqrtf(var + 1e-5f) * gg + bb;
        out[(row0 + r) * C + tid] = gelu_f(y);
    }
}

__global__ void coord_add_kernel(const float* __restrict__ xyz, const float* __restrict__ xagg,
                                 float* __restrict__ coord)
{
    int i = blockIdx.x * 256 + threadIdx.x;
    if (i < NN * 3) coord[i] = xyz[i] + xagg[i];
}

__global__ __launch_bounds__(256) void out_kernel(
    const float* __restrict__ h, const float* __restrict__ W,
    const float* __restrict__ b, float* __restrict__ out)
{
    int n = blockIdx.x * 8 + (threadIdx.x >> 5);
    if (n >= NN) return;
    int lane = threadIdx.x & 31;
    float a0 = 0.f, a1 = 0.f, a2 = 0.f;
#pragma unroll
    for (int q = 0; q < 4; q++) {
        int k = lane + 32 * q;
        float x = h[(size_t)n * C + k];
        a0 += x * W[k * 3 + 0]; a1 += x * W[k * 3 + 1]; a2 += x * W[k * 3 + 2];
    }
#pragma unroll
    for (int o = 16; o > 0; o >>= 1) {
        a0 += __shfl_down_sync(0xffffffffu, a0, o);
        a1 += __shfl_down_sync(0xffffffffu, a1, o);
        a2 += __shfl_down_sync(0xffffffffu, a2, o);
    }
    if (lane == 0) {
        out[n * 3 + 0] = a0 + b[0];
        out[n * 3 + 1] = a1 + b[1];
        out[n * 3 + 2] = a2 + b[2];
    }
}

extern "C" void kernel_launch(void* const* d_in, const int* in_sizes, int n_in,
                              void* d_out, int out_size)
{
    const int*   src       = (const int*)d_in[0];
    const int*   dst       = (const int*)d_in[1];
    const float* node_attr = (const float*)d_in[2];
    const float* xyz       = (const float*)d_in[3];
    const float* emb_w1    = (const float*)d_in[4];
    const float* emb_b1    = (const float*)d_in[5];
    const float* ln1_g     = (const float*)d_in[6];
    const float* ln1_b     = (const float*)d_in[7];
    const float* emb_w2    = (const float*)d_in[8];
    const float* emb_b2    = (const float*)d_in[9];
    const float* ln2_g     = (const float*)d_in[10];
    const float* ln2_b     = (const float*)d_in[11];
    const float* e_w1      = (const float*)d_in[12];
    const float* e_b1      = (const float*)d_in[13];
    const float* e_w2      = (const float*)d_in[14];
    const float* e_b2      = (const float*)d_in[15];
    const float* n_w1      = (const float*)d_in[16];
    const float* n_b1      = (const float*)d_in[17];
    const float* n_w2      = (const float*)d_in[18];
    const float* n_b2      = (const float*)d_in[19];
    const float* c_w1      = (const float*)d_in[20];
    const float* c_b1      = (const float*)d_in[21];
    const float* c_w2      = (const float*)d_in[22];
    const float* dec_ln_g  = (const float*)d_in[23];
    const float* dec_ln_b  = (const float*)d_in[24];
    const float* out_w     = (const float*)d_in[25];
    const float* out_b     = (const float*)d_in[26];
    float* out = (float*)d_out;

    float *h, *hn, *hs, *hd, *hagg, *xagg, *coord;
    cudaGetSymbolAddress((void**)&h, g_h);
    cudaGetSymbolAddress((void**)&hn, g_hn);
    cudaGetSymbolAddress((void**)&hs, g_hs);
    cudaGetSymbolAddress((void**)&hd, g_hd);
    cudaGetSymbolAddress((void**)&hagg, g_hagg);
    cudaGetSymbolAddress((void**)&xagg, g_xagg);
    cudaGetSymbolAddress((void**)&coord, g_coord);

    int dev = 0;
    cudaGetDevice(&dev);
    int nsm = 148;
    cudaDeviceGetAttribute(&nsm, cudaDevAttrMultiProcessorCount, dev);

    cudaFuncSetAttribute((const void*)edge_nc_kernel,
                         cudaFuncAttributeMaxDynamicSharedMemorySize, SMEM_NCT);
    cudaFuncSetAttribute((const void*)edge_co_kernel,
                         cudaFuncAttributeMaxDynamicSharedMemorySize, SMEM_COT);
    cudaFuncSetAttribute((const void*)pre_mma_kernel,
                         cudaFuncAttributeMaxDynamicSharedMemorySize, SMEM_PRE);
    cudaFuncSetAttribute((const void*)node_mma_kernel<false>,
                         cudaFuncAttributeMaxDynamicSharedMemorySize, SMEM_NODE);
    cudaFuncSetAttribute((const void*)node_mma_kernel<true>,
                         cudaFuncAttributeMaxDynamicSharedMemorySize, SMEM_NODE);

    embed_kernel<64><<<NN / 4, 128>>>(node_attr, emb_w1, emb_b1, ln1_g, ln1_b, hn);
    embed_kernel<128><<<NN / 4, 128>>>(hn, emb_w2, emb_b2, ln2_g, ln2_b, h);

    float* hcur = h;
    float* htmp = hn;
    for (int l = 0; l < 3; l++) {
        const float* ew1l = e_w1 + (size_t)l * 257 * C;
        pre_mma_kernel<<<NROWT, 512, SMEM_PRE>>>(hcur, ew1l, hs, hd);
        cudaMemsetAsync(hagg, 0, (size_t)NN * C * sizeof(float));
        const float* Xl = (l == 2) ? coord : xyz;
        if (l == 1) {
            cudaMemsetAsync(xagg, 0, (size_t)NN * 3 * sizeof(float));
            edge_co_kernel<<<nsm, 512, SMEM_COT>>>(
                src, dst, Xl, hs, hd, ew1l + 256 * C, e_b1 + l * C,
                e_w2 + (size_t)l * C * C, e_b2 + l * C,
                c_w1 + (size_t)l * C * C, c_b1 + l * C, c_w2 + l * C, hagg, xagg);
        } else {
            edge_nc_kernel<<<nsm, 512, SMEM_NCT>>>(
                src, dst, Xl, hs, hd, ew1l + 256 * C, e_b1 + l * C,
                e_w2 + (size_t)l * C * C, e_b2 + l * C, hagg);
        }
        if (l == 0)
            node_mma_kernel<false><<<NROWT, 512, SMEM_NODE>>>(hcur, hagg,
                n_w1 + (size_t)l * 256 * C, n_b1 + l * C,
                n_w2 + (size_t)l * C * C, n_b2 + l * C, dec_ln_g, dec_ln_b, htmp);
        else
            node_mma_kernel<true><<<NROWT, 512, SMEM_NODE>>>(hcur, hagg,
                n_w1 + (size_t)l * 256 * C, n_b1 + l * C,
                n_w2 + (size_t)l * C * C, n_b2 + l * C, dec_ln_g, dec_ln_b, htmp);
        float* t = hcur; hcur = htmp; htmp = t;
        if (l == 1) coord_add_kernel<<<(NN * 3 + 255) / 256, 256>>>(xyz, xagg, coord);
    }
    out_kernel<<<(NN + 7) / 8, 256>>>(hcur, out_w, out_b, out);
}